// round 1
// baseline (speedup 1.0000x reference)
#include <cuda_runtime.h>

#define PHYS_DT (1.0f/60.0f)
#define NU_C    0.001f

__device__ __forceinline__ float softplusf(float x){
    return fmaxf(x, 0.0f) + log1pf(expf(-fabsf(x)));
}

// ---------------------------------------------------------------------------
// Particle kernel: one block per batch, one thread per particle (N=64).
// RK4 with pairwise contact forces; contacts stored transposed with stride 65
// (conflict-free LDS both on the transposing write and the j-loop read).
// ---------------------------------------------------------------------------
__global__ void __launch_bounds__(64) particle_kernel(
    const float* __restrict__ pos, const float* __restrict__ vel,
    const float* __restrict__ rot, const float* __restrict__ omg,
    const float* __restrict__ mass, const float* __restrict__ inertia,
    const float* __restrict__ contacts, const float* __restrict__ energy,
    const float* __restrict__ Fext, const float* __restrict__ tau,
    const float* __restrict__ logA, const float* __restrict__ logk,
    const float* __restrict__ logb, float* __restrict__ out)
{
    const int b = blockIdx.x;
    const int i = threadIdx.x;
    __shared__ float4 sp[64];
    __shared__ float4 sv[64];
    __shared__ float  ct[64*65];
    __shared__ float  redw[2];

    const int gi = b*64 + i;
    const float px=pos[gi*3+0], py=pos[gi*3+1], pz=pos[gi*3+2];
    const float vx=vel[gi*3+0], vy=vel[gi*3+1], vz=vel[gi*3+2];
    const float rw=rot[gi*4+0], rx=rot[gi*4+1], ry=rot[gi*4+2], rz=rot[gi*4+3];
    const float ox=omg[gi*3+0], oy=omg[gi*3+1], oz=omg[gi*3+2];
    const float Ix=inertia[gi*3+0], Iy=inertia[gi*3+1], Iz=inertia[gi*3+2];
    const float fx=Fext[gi*3+0], fy=Fext[gi*3+1], fz=Fext[gi*3+2];
    const float tx=tau[gi*3+0], ty=tau[gi*3+1], tz=tau[gi*3+2];
    const float m    = mass[gi];
    const float kk   = softplusf(logk[0]);
    const float bb   = softplusf(logb[0]);
    const float dragc= -0.5f*1.225f*0.47f*softplusf(logA[i]);
    const float minv = 1.0f/m;
    const float Iix=1.0f/fmaxf(Ix,1e-6f), Iiy=1.0f/fmaxf(Iy,1e-6f), Iiz=1.0f/fmaxf(Iz,1e-6f);

    // transpose contacts into shared: read coalesced rows, write stride-65 (conflict-free)
    #pragma unroll 8
    for (int r = 0; r < 64; r++)
        ct[i*65 + r] = contacts[b*4096 + r*64 + i];
    sp[i] = make_float4(px,py,pz,0.f);
    sv[i] = make_float4(vx,vy,vz,0.f);
    __syncthreads();

    // stage state
    float cpx=px,cpy=py,cpz=pz, cvx=vx,cvy=vy,cvz=vz;
    float qw=rw,qx=rx,qy=ry,qz=rz, cox=ox,coy=oy,coz=oz;
    // RK accumulators
    float aPx=0,aPy=0,aPz=0, aVx=0,aVy=0,aVz=0;
    float aRw=0,aRx=0,aRy=0,aRz=0, aWx=0,aWy=0,aWz=0, aE=0;
    // stage derivative outputs
    float dvx,dvy,dvz, drw,drx,dry,drz, dwx,dwy,dwz, dE;

    auto deriv = [&]() {
        float vm = fmaxf(sqrtf(cvx*cvx + cvy*cvy + cvz*cvz), 1e-6f);
        float dc = dragc * vm;
        float fdx = dc*cvx, fdy = dc*cvy, fdz = dc*cvz;
        float fcx = 0.f, fcy = 0.f, fcz = 0.f;
        #pragma unroll 8
        for (int j = 0; j < 64; j++) {
            float4 pj = sp[j];
            float4 vj = sv[j];
            float dx = pj.x - cpx, dy = pj.y - cpy, dz = pj.z - cpz;
            float d2 = fmaf(dx,dx, fmaf(dy,dy, dz*dz));
            float ri = rsqrtf(fmaxf(d2, 1e-12f));
            float pen = fmaxf(1.0f - d2*ri, 0.0f);   // dist = d2 * rsqrt(d2)
            float kp = kk * pen * ri;                // k*pen/dist (dx*kp = k*pen*n_hat)
            float cf = bb * ct[j*65 + i];
            fcx += kp*dx + cf*(vj.x - cvx);
            fcy += kp*dy + cf*(vj.y - cvy);
            fcz += kp*dz + cf*(vj.z - cvz);
        }
        dvx = (fx + fdx + fcx) * minv;
        dvy = (fy + fdy + fcy) * minv;
        dvz = (fz + fdz + fcz) * minv - 9.81f;
        float Iox = Ix*cox, Ioy = Iy*coy, Ioz = Iz*coz;
        dwx = (tx - (coy*Ioz - coz*Ioy)) * Iix;
        dwy = (ty - (coz*Iox - cox*Ioz)) * Iiy;
        dwz = (tz - (cox*Ioy - coy*Iox)) * Iiz;
        drw = 0.5f*(-qx*cox - qy*coy - qz*coz);
        drx = 0.5f*( qw*cox + qy*coz - qz*coy);
        dry = 0.5f*( qw*coy - qx*coz + qz*cox);
        drz = 0.5f*( qw*coz + qx*coy - qy*cox);
        dE  = (fx + fdx)*cvx + (fy + fdy)*cvy + (fz + fdz)*cvz;
    };

    auto accum = [&](float w) {
        aPx += w*cvx; aPy += w*cvy; aPz += w*cvz;
        aVx += w*dvx; aVy += w*dvy; aVz += w*dvz;
        aRw += w*drw; aRx += w*drx; aRy += w*dry; aRz += w*drz;
        aWx += w*dwx; aWy += w*dwy; aWz += w*dwz;
        aE  += w*dE;
    };

    auto advance = [&](float h) {
        float npx = px + h*cvx, npy = py + h*cvy, npz = pz + h*cvz;  // uses stage vel (k[0])
        cvx = vx + h*dvx; cvy = vy + h*dvy; cvz = vz + h*dvz;
        cpx = npx; cpy = npy; cpz = npz;
        float nqw = rw + h*drw, nqx = rx + h*drx, nqy = ry + h*dry, nqz = rz + h*drz;
        float nn  = fmaxf(sqrtf(nqw*nqw + nqx*nqx + nqy*nqy + nqz*nqz), 1e-12f);
        float inn = 1.0f/nn;
        qw = nqw*inn; qx = nqx*inn; qy = nqy*inn; qz = nqz*inn;
        cox = ox + h*dwx; coy = oy + h*dwy; coz = oz + h*dwz;
        __syncthreads();                 // all readers done with previous stage
        sp[i] = make_float4(cpx,cpy,cpz,0.f);
        sv[i] = make_float4(cvx,cvy,cvz,0.f);
        __syncthreads();                 // new stage visible
    };

    const int base = b * 13313;

    deriv(); accum(1.f);
    {   // nforces = Fext + mass * k1.dv  (written once, never touched again)
        int fb = base + 832 + i*3;
        out[fb+0] = fx + m*dvx;
        out[fb+1] = fy + m*dvy;
        out[fb+2] = fz + m*dvz;
    }
    advance(0.5f*PHYS_DT);
    deriv(); accum(2.f);
    advance(0.5f*PHYS_DT);
    deriv(); accum(2.f);
    advance(PHYS_DT);
    deriv(); accum(1.f);

    const float s6 = PHYS_DT/6.0f;
    out[base + i*3+0] = px + s6*aPx;
    out[base + i*3+1] = py + s6*aPy;
    out[base + i*3+2] = pz + s6*aPz;
    out[base + 192 + i*3+0] = vx + s6*aVx;
    out[base + 192 + i*3+1] = vy + s6*aVy;
    out[base + 192 + i*3+2] = vz + s6*aVz;
    {
        float nqw = rw + s6*aRw, nqx = rx + s6*aRx, nqy = ry + s6*aRy, nqz = rz + s6*aRz;
        float nn  = fmaxf(sqrtf(nqw*nqw + nqx*nqx + nqy*nqy + nqz*nqz), 1e-12f);
        float inn = 1.0f/nn;
        out[base + 384 + i*4+0] = nqw*inn;
        out[base + 384 + i*4+1] = nqx*inn;
        out[base + 384 + i*4+2] = nqy*inn;
        out[base + 384 + i*4+3] = nqz*inn;
    }
    out[base + 640 + i*3+0] = ox + s6*aWx;
    out[base + 640 + i*3+1] = oy + s6*aWy;
    out[base + 640 + i*3+2] = oz + s6*aWz;

    // deterministic energy reduction: shfl tree per warp + fixed-order combine
    float e = aE;
    #pragma unroll
    for (int off = 16; off; off >>= 1)
        e += __shfl_down_sync(0xffffffffu, e, off);
    if ((i & 31) == 0) redw[i >> 5] = e;
    __syncthreads();
    if (i == 0) out[base + 1024] = energy[b] + s6*(redw[0] + redw[1]);
}

// ---------------------------------------------------------------------------
// Fluid kernel: one block per batch, 256 threads = (d = tid>>4, w = tid&15),
// each thread sweeps h = 0..15 for all 3 components.
// Depthwise 3x3x3 conv via h-sliding register window (3 LDS per output) and
// w-direction via warp shuffles with zero-pad edge masks. Double-buffered
// stage state in dynamic shared: layout [c][d][h][w], w contiguous (RS=16),
// slice stride SS=272 (padded -> conflict-free across the 2 d's in a warp).
// ---------------------------------------------------------------------------
__global__ void __launch_bounds__(256) fluid_kernel(
    const float* __restrict__ fluid, const float* __restrict__ conv_w,
    float* __restrict__ out)
{
    extern __shared__ float S[];          // 2 * 13056 floats
    __shared__ float Wsh[81];
    __shared__ float redsh[24];
    __shared__ float meansh[3];

    const int b = blockIdx.x, tid = threadIdx.x;
    const int d = tid >> 4, w = tid & 15;
    const int RS = 16, SS = 272, CS = 4352, BUF = 13056;
    const float* fb = fluid + b*12288;

    if (tid < 81) Wsh[tid] = conv_w[tid];

    // coalesced load of u0 into buffer 0 (scattered padded-shared writes)
    for (int idx = tid; idx < 12288; idx += 256) {
        float val = fb[idx];
        int cell = idx / 3, c = idx - cell*3;
        int dd = cell >> 8, hh = (cell >> 4) & 15, ww = cell & 15;
        S[c*CS + dd*SS + hh*RS + ww] = val;
    }
    __syncthreads();

    float acc[48];
    #pragma unroll
    for (int q = 0; q < 48; q++) acc[q] = 0.f;

    const bool dmv = (d > 0), dpv = (d < 15);
    const float accw[4]  = {1.f, 2.f, 2.f, 1.f};
    const float coeff[3] = {0.5f*PHYS_DT, 0.5f*PHYS_DT, PHYS_DT};

    #pragma unroll 1
    for (int s = 0; s < 4; s++) {
        const float* cur = S + (s & 1)*BUF;
        float*       nxt = S + ((s + 1) & 1)*BUF;
        const float  aw  = accw[s];
        const float  co  = (s < 3) ? coeff[s] : 0.f;
        float ps0 = 0.f, ps1 = 0.f, ps2 = 0.f;

        #pragma unroll
        for (int c = 0; c < 3; c++) {
            float W[27];
            #pragma unroll
            for (int t = 0; t < 27; t++) W[t] = Wsh[c*27 + t];
            const float* b0p = cur + c*CS + d*SS + w;

            // sliding window r[kd][t]: t=0 -> h-1, t=1 -> h, t=2 -> h+1
            float r00 = 0.f, r10 = 0.f, r20 = 0.f;
            float r01 = dmv ? b0p[-SS]       : 0.f;
            float r11 =        b0p[0];
            float r21 = dpv ? b0p[ SS]       : 0.f;
            float r02 = dmv ? b0p[-SS + RS]  : 0.f;
            float r12 =        b0p[RS];
            float r22 = dpv ? b0p[ SS + RS]  : 0.f;
            float psc = 0.f;

            #pragma unroll
            for (int h = 0; h < 16; h++) {
                float bb0 = W[ 0]*r00 + W[ 3]*r01 + W[ 6]*r02
                          + W[ 9]*r10 + W[12]*r11 + W[15]*r12
                          + W[18]*r20 + W[21]*r21 + W[24]*r22;
                float bb1 = W[ 1]*r00 + W[ 4]*r01 + W[ 7]*r02
                          + W[10]*r10 + W[13]*r11 + W[16]*r12
                          + W[19]*r20 + W[22]*r21 + W[25]*r22;
                float bb2 = W[ 2]*r00 + W[ 5]*r01 + W[ 8]*r02
                          + W[11]*r10 + W[14]*r11 + W[17]*r12
                          + W[20]*r20 + W[23]*r21 + W[26]*r22;
                float lft = __shfl_up_sync(0xffffffffu, bb0, 1);
                if (w == 0)  lft = 0.f;                     // zero pad (and d-boundary in warp)
                float rgt = __shfl_down_sync(0xffffffffu, bb2, 1);
                if (w == 15) rgt = 0.f;
                float kv = NU_C * (lft + bb1 + rgt);
                acc[c*16 + h] += aw * kv;
                if (s < 3) {
                    float u0v = fb[(((d << 8) + (h << 4) + w) * 3) + c];
                    float sr = u0v + co * kv;
                    nxt[c*CS + d*SS + h*RS + w] = sr;
                    psc += sr;
                }
                // slide window in h
                r00 = r01; r01 = r02;
                r10 = r11; r11 = r12;
                r20 = r21; r21 = r22;
                if (h < 14) {
                    r02 = dmv ? b0p[-SS + (h+2)*RS] : 0.f;
                    r12 =        b0p[      (h+2)*RS];
                    r22 = dpv ? b0p[ SS + (h+2)*RS] : 0.f;
                } else {
                    r02 = 0.f; r12 = 0.f; r22 = 0.f;
                }
            }
            if      (c == 0) ps0 = psc;
            else if (c == 1) ps1 = psc;
            else             ps2 = psc;
        }

        if (s < 3) {
            // deterministic per-component mean over 4096 cells
            #pragma unroll
            for (int off = 16; off; off >>= 1) {
                ps0 += __shfl_xor_sync(0xffffffffu, ps0, off);
                ps1 += __shfl_xor_sync(0xffffffffu, ps1, off);
                ps2 += __shfl_xor_sync(0xffffffffu, ps2, off);
            }
            int wi = tid >> 5;
            if ((tid & 31) == 0) {
                redsh[wi*3+0] = ps0; redsh[wi*3+1] = ps1; redsh[wi*3+2] = ps2;
            }
            __syncthreads();
            if (tid < 3) {
                float sm = 0.f;
                #pragma unroll
                for (int q = 0; q < 8; q++) sm += redsh[q*3 + tid];
                meansh[tid] = sm * (1.0f/4096.0f);
            }
            __syncthreads();
            // subtract mean from own cells
            #pragma unroll
            for (int c = 0; c < 3; c++) {
                float mc = meansh[c];
                #pragma unroll
                for (int h = 0; h < 16; h++)
                    nxt[c*CS + d*SS + h*RS + w] -= mc;
            }
            __syncthreads();   // stage state final -> becomes next cur
        }
    }

    // final combine: raw = u0 + dt/6 * acc, then demean, then coalesced store
    float pf0 = 0.f, pf1 = 0.f, pf2 = 0.f;
    const float s6 = PHYS_DT/6.0f;
    #pragma unroll
    for (int c = 0; c < 3; c++) {
        float psc = 0.f;
        #pragma unroll
        for (int h = 0; h < 16; h++) {
            float u0v = fb[(((d << 8) + (h << 4) + w) * 3) + c];
            float rv = u0v + s6 * acc[c*16 + h];
            S[c*CS + d*SS + h*RS + w] = rv;     // buffer 0 is free after stage 3
            psc += rv;
        }
        if      (c == 0) pf0 = psc;
        else if (c == 1) pf1 = psc;
        else             pf2 = psc;
    }
    #pragma unroll
    for (int off = 16; off; off >>= 1) {
        pf0 += __shfl_xor_sync(0xffffffffu, pf0, off);
        pf1 += __shfl_xor_sync(0xffffffffu, pf1, off);
        pf2 += __shfl_xor_sync(0xffffffffu, pf2, off);
    }
    {
        int wi = tid >> 5;
        if ((tid & 31) == 0) {
            redsh[wi*3+0] = pf0; redsh[wi*3+1] = pf1; redsh[wi*3+2] = pf2;
        }
    }
    __syncthreads();
    if (tid < 3) {
        float sm = 0.f;
        #pragma unroll
        for (int q = 0; q < 8; q++) sm += redsh[q*3 + tid];
        meansh[tid] = sm * (1.0f/4096.0f);
    }
    __syncthreads();
    #pragma unroll
    for (int c = 0; c < 3; c++) {
        float mc = meansh[c];
        #pragma unroll
        for (int h = 0; h < 16; h++)
            S[c*CS + d*SS + h*RS + w] -= mc;
    }
    __syncthreads();

    float* ob = out + b*13313 + 1025;
    for (int idx = tid; idx < 12288; idx += 256) {
        int cell = idx / 3, c = idx - cell*3;
        int dd = cell >> 8, hh = (cell >> 4) & 15, ww = cell & 15;
        ob[idx] = S[c*CS + dd*SS + hh*RS + ww];
    }
}

// ---------------------------------------------------------------------------
extern "C" void kernel_launch(void* const* d_in, const int* in_sizes, int n_in,
                              void* d_out, int out_size)
{
    (void)in_sizes; (void)n_in; (void)out_size;
    const float* pos      = (const float*)d_in[0];
    const float* vel      = (const float*)d_in[1];
    const float* rot      = (const float*)d_in[2];
    const float* omg      = (const float*)d_in[3];
    const float* mass     = (const float*)d_in[4];
    const float* inertia  = (const float*)d_in[5];
    const float* contacts = (const float*)d_in[6];
    const float* energy   = (const float*)d_in[7];
    const float* fluid    = (const float*)d_in[8];
    const float* Fext     = (const float*)d_in[9];
    const float* tau      = (const float*)d_in[10];
    const float* logA     = (const float*)d_in[11];
    const float* logk     = (const float*)d_in[12];
    const float* logb     = (const float*)d_in[13];
    const float* conv_w   = (const float*)d_in[14];
    float* out = (float*)d_out;

    const int fluid_smem = 2 * 13056 * (int)sizeof(float);   // 104448 B
    cudaFuncSetAttribute(fluid_kernel,
                         cudaFuncAttributeMaxDynamicSharedMemorySize, fluid_smem);

    particle_kernel<<<512, 64>>>(pos, vel, rot, omg, mass, inertia, contacts,
                                 energy, Fext, tau, logA, logk, logb, out);
    fluid_kernel<<<512, 256, fluid_smem>>>(fluid, conv_w, out);
}

// round 2
// speedup vs baseline: 1.0223x; 1.0223x over previous
#include <cuda_runtime.h>

#define PHYS_DT (1.0f/60.0f)
#define NU_C    0.001f

__device__ __forceinline__ float softplusf(float x){
    return fmaxf(x, 0.0f) + log1pf(expf(-fabsf(x)));
}

// ---------------------------------------------------------------------------
// Particle kernel: one block per batch, one thread per particle (N=64).
// RK4 with pairwise contact forces; contacts stored transposed with stride 65
// (conflict-free LDS both on the transposing write and the j-loop read).
// ---------------------------------------------------------------------------
__global__ void __launch_bounds__(64) particle_kernel(
    const float* __restrict__ pos, const float* __restrict__ vel,
    const float* __restrict__ rot, const float* __restrict__ omg,
    const float* __restrict__ mass, const float* __restrict__ inertia,
    const float* __restrict__ contacts, const float* __restrict__ energy,
    const float* __restrict__ Fext, const float* __restrict__ tau,
    const float* __restrict__ logA, const float* __restrict__ logk,
    const float* __restrict__ logb, float* __restrict__ out)
{
    const int b = blockIdx.x;
    const int i = threadIdx.x;
    __shared__ float4 sp[64];
    __shared__ float4 sv[64];
    __shared__ float  ct[64*65];
    __shared__ float  redw[2];

    const int gi = b*64 + i;
    const float px=pos[gi*3+0], py=pos[gi*3+1], pz=pos[gi*3+2];
    const float vx=vel[gi*3+0], vy=vel[gi*3+1], vz=vel[gi*3+2];
    const float rw=rot[gi*4+0], rx=rot[gi*4+1], ry=rot[gi*4+2], rz=rot[gi*4+3];
    const float ox=omg[gi*3+0], oy=omg[gi*3+1], oz=omg[gi*3+2];
    const float Ix=inertia[gi*3+0], Iy=inertia[gi*3+1], Iz=inertia[gi*3+2];
    const float fx=Fext[gi*3+0], fy=Fext[gi*3+1], fz=Fext[gi*3+2];
    const float tx=tau[gi*3+0], ty=tau[gi*3+1], tz=tau[gi*3+2];
    const float m    = mass[gi];
    const float kk   = softplusf(logk[0]);
    const float bb   = softplusf(logb[0]);
    const float dragc= -0.5f*1.225f*0.47f*softplusf(logA[i]);
    const float minv = 1.0f/m;
    const float Iix=1.0f/fmaxf(Ix,1e-6f), Iiy=1.0f/fmaxf(Iy,1e-6f), Iiz=1.0f/fmaxf(Iz,1e-6f);

    // transpose contacts into shared: read coalesced rows, write stride-65 (conflict-free)
    #pragma unroll 8
    for (int r = 0; r < 64; r++)
        ct[i*65 + r] = contacts[b*4096 + r*64 + i];
    sp[i] = make_float4(px,py,pz,0.f);
    sv[i] = make_float4(vx,vy,vz,0.f);
    __syncthreads();

    // stage state
    float cpx=px,cpy=py,cpz=pz, cvx=vx,cvy=vy,cvz=vz;
    float qw=rw,qx=rx,qy=ry,qz=rz, cox=ox,coy=oy,coz=oz;
    // RK accumulators
    float aPx=0,aPy=0,aPz=0, aVx=0,aVy=0,aVz=0;
    float aRw=0,aRx=0,aRy=0,aRz=0, aWx=0,aWy=0,aWz=0, aE=0;
    // stage derivative outputs
    float dvx,dvy,dvz, drw,drx,dry,drz, dwx,dwy,dwz, dE;

    auto deriv = [&]() {
        float vm = fmaxf(sqrtf(cvx*cvx + cvy*cvy + cvz*cvz), 1e-6f);
        float dc = dragc * vm;
        float fdx = dc*cvx, fdy = dc*cvy, fdz = dc*cvz;
        float fcx = 0.f, fcy = 0.f, fcz = 0.f;
        #pragma unroll 8
        for (int j = 0; j < 64; j++) {
            float4 pj = sp[j];
            float4 vj = sv[j];
            float dx = pj.x - cpx, dy = pj.y - cpy, dz = pj.z - cpz;
            float d2 = fmaf(dx,dx, fmaf(dy,dy, dz*dz));
            float ri = rsqrtf(fmaxf(d2, 1e-12f));
            float pen = fmaxf(1.0f - d2*ri, 0.0f);   // dist = d2 * rsqrt(d2)
            float kp = kk * pen * ri;                // k*pen/dist (dx*kp = k*pen*n_hat)
            float cf = bb * ct[j*65 + i];
            fcx += kp*dx + cf*(vj.x - cvx);
            fcy += kp*dy + cf*(vj.y - cvy);
            fcz += kp*dz + cf*(vj.z - cvz);
        }
        dvx = (fx + fdx + fcx) * minv;
        dvy = (fy + fdy + fcy) * minv;
        dvz = (fz + fdz + fcz) * minv - 9.81f;
        float Iox = Ix*cox, Ioy = Iy*coy, Ioz = Iz*coz;
        dwx = (tx - (coy*Ioz - coz*Ioy)) * Iix;
        dwy = (ty - (coz*Iox - cox*Ioz)) * Iiy;
        dwz = (tz - (cox*Ioy - coy*Iox)) * Iiz;
        drw = 0.5f*(-qx*cox - qy*coy - qz*coz);
        drx = 0.5f*( qw*cox + qy*coz - qz*coy);
        dry = 0.5f*( qw*coy - qx*coz + qz*cox);
        drz = 0.5f*( qw*coz + qx*coy - qy*cox);
        dE  = (fx + fdx)*cvx + (fy + fdy)*cvy + (fz + fdz)*cvz;
    };

    auto accum = [&](float w) {
        aPx += w*cvx; aPy += w*cvy; aPz += w*cvz;
        aVx += w*dvx; aVy += w*dvy; aVz += w*dvz;
        aRw += w*drw; aRx += w*drx; aRy += w*dry; aRz += w*drz;
        aWx += w*dwx; aWy += w*dwy; aWz += w*dwz;
        aE  += w*dE;
    };

    auto advance = [&](float h) {
        float npx = px + h*cvx, npy = py + h*cvy, npz = pz + h*cvz;  // uses stage vel (k[0])
        cvx = vx + h*dvx; cvy = vy + h*dvy; cvz = vz + h*dvz;
        cpx = npx; cpy = npy; cpz = npz;
        float nqw = rw + h*drw, nqx = rx + h*drx, nqy = ry + h*dry, nqz = rz + h*drz;
        float nn  = fmaxf(sqrtf(nqw*nqw + nqx*nqx + nqy*nqy + nqz*nqz), 1e-12f);
        float inn = 1.0f/nn;
        qw = nqw*inn; qx = nqx*inn; qy = nqy*inn; qz = nqz*inn;
        cox = ox + h*dwx; coy = oy + h*dwy; coz = oz + h*dwz;
        __syncthreads();                 // all readers done with previous stage
        sp[i] = make_float4(cpx,cpy,cpz,0.f);
        sv[i] = make_float4(cvx,cvy,cvz,0.f);
        __syncthreads();                 // new stage visible
    };

    const int base = b * 13313;

    deriv(); accum(1.f);
    {   // nforces = Fext + mass * k1.dv  (written once, never touched again)
        int fb = base + 832 + i*3;
        out[fb+0] = fx + m*dvx;
        out[fb+1] = fy + m*dvy;
        out[fb+2] = fz + m*dvz;
    }
    advance(0.5f*PHYS_DT);
    deriv(); accum(2.f);
    advance(0.5f*PHYS_DT);
    deriv(); accum(2.f);
    advance(PHYS_DT);
    deriv(); accum(1.f);

    const float s6 = PHYS_DT/6.0f;
    out[base + i*3+0] = px + s6*aPx;
    out[base + i*3+1] = py + s6*aPy;
    out[base + i*3+2] = pz + s6*aPz;
    out[base + 192 + i*3+0] = vx + s6*aVx;
    out[base + 192 + i*3+1] = vy + s6*aVy;
    out[base + 192 + i*3+2] = vz + s6*aVz;
    {
        float nqw = rw + s6*aRw, nqx = rx + s6*aRx, nqy = ry + s6*aRy, nqz = rz + s6*aRz;
        float nn  = fmaxf(sqrtf(nqw*nqw + nqx*nqx + nqy*nqy + nqz*nqz), 1e-12f);
        float inn = 1.0f/nn;
        out[base + 384 + i*4+0] = nqw*inn;
        out[base + 384 + i*4+1] = nqx*inn;
        out[base + 384 + i*4+2] = nqy*inn;
        out[base + 384 + i*4+3] = nqz*inn;
    }
    out[base + 640 + i*3+0] = ox + s6*aWx;
    out[base + 640 + i*3+1] = oy + s6*aWy;
    out[base + 640 + i*3+2] = oz + s6*aWz;

    // deterministic energy reduction: shfl tree per warp + fixed-order combine
    float e = aE;
    #pragma unroll
    for (int off = 16; off; off >>= 1)
        e += __shfl_down_sync(0xffffffffu, e, off);
    if ((i & 31) == 0) redw[i >> 5] = e;
    __syncthreads();
    if (i == 0) out[base + 1024] = energy[b] + s6*(redw[0] + redw[1]);
}

// ---------------------------------------------------------------------------
// Fluid kernel: one block per batch, 256 threads = (d = tid>>4, w = tid&15),
// each thread sweeps h = 0..15 for all 3 components.
// Depthwise 3x3x3 conv via h-sliding register window (3 LDS per output) and
// w-direction via warp shuffles with zero-pad edge masks. Double-buffered
// stage state in dynamic shared: layout [c][d][h][w], w contiguous (RS=16),
// slice stride SS=272 (padded -> conflict-free across the 2 d's in a warp).
// ---------------------------------------------------------------------------
__global__ void __launch_bounds__(256) fluid_kernel(
    const float* __restrict__ fluid, const float* __restrict__ conv_w,
    float* __restrict__ out)
{
    extern __shared__ float S[];          // 2 * 13056 floats
    __shared__ float Wsh[81];
    __shared__ float redsh[24];
    __shared__ float meansh[3];

    const int b = blockIdx.x, tid = threadIdx.x;
    const int d = tid >> 4, w = tid & 15;
    const int RS = 16, SS = 272, CS = 4352, BUF = 13056;
    const float* fb = fluid + b*12288;

    if (tid < 81) Wsh[tid] = conv_w[tid];

    // coalesced load of u0 into buffer 0 (scattered padded-shared writes)
    for (int idx = tid; idx < 12288; idx += 256) {
        float val = fb[idx];
        int cell = idx / 3, c = idx - cell*3;
        int dd = cell >> 8, hh = (cell >> 4) & 15, ww = cell & 15;
        S[c*CS + dd*SS + hh*RS + ww] = val;
    }
    __syncthreads();

    float acc[48];
    #pragma unroll
    for (int q = 0; q < 48; q++) acc[q] = 0.f;

    const bool dmv = (d > 0), dpv = (d < 15);
    const float accw[4]  = {1.f, 2.f, 2.f, 1.f};
    const float coeff[3] = {0.5f*PHYS_DT, 0.5f*PHYS_DT, PHYS_DT};

    #pragma unroll 1
    for (int s = 0; s < 4; s++) {
        const float* cur = S + (s & 1)*BUF;
        float*       nxt = S + ((s + 1) & 1)*BUF;
        const float  aw  = accw[s];
        const float  co  = (s < 3) ? coeff[s] : 0.f;
        float ps0 = 0.f, ps1 = 0.f, ps2 = 0.f;

        #pragma unroll
        for (int c = 0; c < 3; c++) {
            float W[27];
            #pragma unroll
            for (int t = 0; t < 27; t++) W[t] = Wsh[c*27 + t];
            const float* b0p = cur + c*CS + d*SS + w;

            // sliding window r[kd][t]: t=0 -> h-1, t=1 -> h, t=2 -> h+1
            float r00 = 0.f, r10 = 0.f, r20 = 0.f;
            float r01 = dmv ? b0p[-SS]       : 0.f;
            float r11 =        b0p[0];
            float r21 = dpv ? b0p[ SS]       : 0.f;
            float r02 = dmv ? b0p[-SS + RS]  : 0.f;
            float r12 =        b0p[RS];
            float r22 = dpv ? b0p[ SS + RS]  : 0.f;
            float psc = 0.f;

            #pragma unroll
            for (int h = 0; h < 16; h++) {
                float bb0 = W[ 0]*r00 + W[ 3]*r01 + W[ 6]*r02
                          + W[ 9]*r10 + W[12]*r11 + W[15]*r12
                          + W[18]*r20 + W[21]*r21 + W[24]*r22;
                float bb1 = W[ 1]*r00 + W[ 4]*r01 + W[ 7]*r02
                          + W[10]*r10 + W[13]*r11 + W[16]*r12
                          + W[19]*r20 + W[22]*r21 + W[25]*r22;
                float bb2 = W[ 2]*r00 + W[ 5]*r01 + W[ 8]*r02
                          + W[11]*r10 + W[14]*r11 + W[17]*r12
                          + W[20]*r20 + W[23]*r21 + W[26]*r22;
                float lft = __shfl_up_sync(0xffffffffu, bb0, 1);
                if (w == 0)  lft = 0.f;                     // zero pad (and d-boundary in warp)
                float rgt = __shfl_down_sync(0xffffffffu, bb2, 1);
                if (w == 15) rgt = 0.f;
                float kv = NU_C * (lft + bb1 + rgt);
                acc[c*16 + h] += aw * kv;
                if (s < 3) {
                    float u0v = fb[(((d << 8) + (h << 4) + w) * 3) + c];
                    float sr = u0v + co * kv;
                    nxt[c*CS + d*SS + h*RS + w] = sr;
                    psc += sr;
                }
                // slide window in h
                r00 = r01; r01 = r02;
                r10 = r11; r11 = r12;
                r20 = r21; r21 = r22;
                if (h < 14) {
                    r02 = dmv ? b0p[-SS + (h+2)*RS] : 0.f;
                    r12 =        b0p[      (h+2)*RS];
                    r22 = dpv ? b0p[ SS + (h+2)*RS] : 0.f;
                } else {
                    r02 = 0.f; r12 = 0.f; r22 = 0.f;
                }
            }
            if      (c == 0) ps0 = psc;
            else if (c == 1) ps1 = psc;
            else             ps2 = psc;
        }

        if (s < 3) {
            // deterministic per-component mean over 4096 cells
            #pragma unroll
            for (int off = 16; off; off >>= 1) {
                ps0 += __shfl_xor_sync(0xffffffffu, ps0, off);
                ps1 += __shfl_xor_sync(0xffffffffu, ps1, off);
                ps2 += __shfl_xor_sync(0xffffffffu, ps2, off);
            }
            int wi = tid >> 5;
            if ((tid & 31) == 0) {
                redsh[wi*3+0] = ps0; redsh[wi*3+1] = ps1; redsh[wi*3+2] = ps2;
            }
            __syncthreads();
            if (tid < 3) {
                float sm = 0.f;
                #pragma unroll
                for (int q = 0; q < 8; q++) sm += redsh[q*3 + tid];
                meansh[tid] = sm * (1.0f/4096.0f);
            }
            __syncthreads();
            // subtract mean from own cells
            #pragma unroll
            for (int c = 0; c < 3; c++) {
                float mc = meansh[c];
                #pragma unroll
                for (int h = 0; h < 16; h++)
                    nxt[c*CS + d*SS + h*RS + w] -= mc;
            }
            __syncthreads();   // stage state final -> becomes next cur
        }
    }

    // final combine: raw = u0 + dt/6 * acc, then demean, then coalesced store
    float pf0 = 0.f, pf1 = 0.f, pf2 = 0.f;
    const float s6 = PHYS_DT/6.0f;
    #pragma unroll
    for (int c = 0; c < 3; c++) {
        float psc = 0.f;
        #pragma unroll
        for (int h = 0; h < 16; h++) {
            float u0v = fb[(((d << 8) + (h << 4) + w) * 3) + c];
            float rv = u0v + s6 * acc[c*16 + h];
            S[c*CS + d*SS + h*RS + w] = rv;     // buffer 0 is free after stage 3
            psc += rv;
        }
        if      (c == 0) pf0 = psc;
        else if (c == 1) pf1 = psc;
        else             pf2 = psc;
    }
    #pragma unroll
    for (int off = 16; off; off >>= 1) {
        pf0 += __shfl_xor_sync(0xffffffffu, pf0, off);
        pf1 += __shfl_xor_sync(0xffffffffu, pf1, off);
        pf2 += __shfl_xor_sync(0xffffffffu, pf2, off);
    }
    {
        int wi = tid >> 5;
        if ((tid & 31) == 0) {
            redsh[wi*3+0] = pf0; redsh[wi*3+1] = pf1; redsh[wi*3+2] = pf2;
        }
    }
    __syncthreads();
    if (tid < 3) {
        float sm = 0.f;
        #pragma unroll
        for (int q = 0; q < 8; q++) sm += redsh[q*3 + tid];
        meansh[tid] = sm * (1.0f/4096.0f);
    }
    __syncthreads();
    #pragma unroll
    for (int c = 0; c < 3; c++) {
        float mc = meansh[c];
        #pragma unroll
        for (int h = 0; h < 16; h++)
            S[c*CS + d*SS + h*RS + w] -= mc;
    }
    __syncthreads();

    float* ob = out + b*13313 + 1025;
    for (int idx = tid; idx < 12288; idx += 256) {
        int cell = idx / 3, c = idx - cell*3;
        int dd = cell >> 8, hh = (cell >> 4) & 15, ww = cell & 15;
        ob[idx] = S[c*CS + dd*SS + hh*RS + ww];
    }
}

// ---------------------------------------------------------------------------
extern "C" void kernel_launch(void* const* d_in, const int* in_sizes, int n_in,
                              void* d_out, int out_size)
{
    (void)in_sizes; (void)n_in; (void)out_size;
    const float* pos      = (const float*)d_in[0];
    const float* vel      = (const float*)d_in[1];
    const float* rot      = (const float*)d_in[2];
    const float* omg      = (const float*)d_in[3];
    const float* mass     = (const float*)d_in[4];
    const float* inertia  = (const float*)d_in[5];
    const float* contacts = (const float*)d_in[6];
    const float* energy   = (const float*)d_in[7];
    const float* fluid    = (const float*)d_in[8];
    const float* Fext     = (const float*)d_in[9];
    const float* tau      = (const float*)d_in[10];
    const float* logA     = (const float*)d_in[11];
    const float* logk     = (const float*)d_in[12];
    const float* logb     = (const float*)d_in[13];
    const float* conv_w   = (const float*)d_in[14];
    float* out = (float*)d_out;

    const int fluid_smem = 2 * 13056 * (int)sizeof(float);   // 104448 B
    cudaFuncSetAttribute(fluid_kernel,
                         cudaFuncAttributeMaxDynamicSharedMemorySize, fluid_smem);

    particle_kernel<<<512, 64>>>(pos, vel, rot, omg, mass, inertia, contacts,
                                 energy, Fext, tau, logA, logk, logb, out);
    fluid_kernel<<<512, 256, fluid_smem>>>(fluid, conv_w, out);
}